// round 14
// baseline (speedup 1.0000x reference)
#include <cuda_runtime.h>
#include <cuda_fp16.h>
#include <cstdint>

#define NPTS 65536
#define NE 8
#define DIN 90
#define NH 256
#define DOUT 4
#define XROW 93
#define TILE_P 128
#define KPAD 96
#define THREADS 256
#define GRID_P 148

// smem byte offsets (strides 208B=13*16, 528B=33*16 -> ldmatrix conflict-free)
#define SH_W1   0           // W1T [256][104h]    53,248B (expert-resident)
#define SH_W2   53248       // W2T [256][264h]   135,168B (expert-resident)
#define SH_W3T  188416      // W3T [8][264h]       4,224B (rows 0-3 data, 4-7 zero), ldsm.x2
#define SH_F    196864      // F   [128][104h]    26,624B (per tile)
#define SH_B1   223488      // b1 f32 [256]
#define SH_B2   224512      // b2 f32 [256]
#define SH_B3   225536      // b3 f32 [4]
#define SH_IDX  225552      // idx [2][128] int
#define SMEM_BYTES 226576

// -------- device scratch --------
__device__ float  g_w[NPTS * NE];
__device__ int    g_idx[NE * NPTS];
__device__ int    g_cnt[NE];
__device__ __half g_xh[NPTS * KPAD];
__device__ __half g_w1t[NE * NH * KPAD];
__device__ __half g_w2t[NE * NH * NH];
__device__ int    g_bar_cnt = 0;
__device__ int    g_bar_gen = 0;

#define WCONV_TOTAL (NE * NH * KPAD + NE * NH * NH)
#define ROUTE_SLABS (NPTS / 128)   // 512

// -------- PTX helpers --------
__device__ __forceinline__ uint32_t smem_u32(const void* p) {
    uint32_t a;
    asm("{ .reg .u64 t; cvta.to.shared.u64 t, %1; cvt.u32.u64 %0, t; }" : "=r"(a) : "l"(p));
    return a;
}
__device__ __forceinline__ void ldsm4(uint32_t& r0, uint32_t& r1, uint32_t& r2, uint32_t& r3,
                                      uint32_t addr) {
    asm volatile("ldmatrix.sync.aligned.m8n8.x4.shared.b16 {%0,%1,%2,%3}, [%4];"
                 : "=r"(r0), "=r"(r1), "=r"(r2), "=r"(r3) : "r"(addr));
}
__device__ __forceinline__ void ldsm2(uint32_t& r0, uint32_t& r1, uint32_t addr) {
    asm volatile("ldmatrix.sync.aligned.m8n8.x2.shared.b16 {%0,%1}, [%2];"
                 : "=r"(r0), "=r"(r1) : "r"(addr));
}
__device__ __forceinline__ void mma16816(float* c, const uint32_t* a, uint32_t b0, uint32_t b1) {
    asm volatile(
        "mma.sync.aligned.m16n8k16.row.col.f32.f16.f16.f32 "
        "{%0,%1,%2,%3}, {%4,%5,%6,%7}, {%8,%9}, {%0,%1,%2,%3};"
        : "+f"(c[0]), "+f"(c[1]), "+f"(c[2]), "+f"(c[3])
        : "r"(a[0]), "r"(a[1]), "r"(a[2]), "r"(a[3]), "r"(b0), "r"(b1));
}
__device__ __forceinline__ void cpa16(uint32_t dst, const void* src) {
    asm volatile("cp.async.cg.shared.global [%0], [%1], 16;" :: "r"(dst), "l"(src));
}
__device__ __forceinline__ void cpa_commit() { asm volatile("cp.async.commit_group;"); }
__device__ __forceinline__ void cpa_wait0() { asm volatile("cp.async.wait_group 0;" ::: "memory"); }
__device__ __forceinline__ uint32_t pack2(float a, float b) {
    __half2 h = __floats2half2_rn(a, b);
    return *(uint32_t*)&h;
}

// -------- grid-wide barrier (148 co-resident CTAs; generation counter) --------
__device__ __forceinline__ void grid_barrier(int t) {
    __syncthreads();
    if (t == 0) {
        int my = *((volatile int*)&g_bar_gen);
        __threadfence();
        int ticket = atomicAdd(&g_bar_cnt, 1);
        if (ticket == GRID_P - 1) {
            g_bar_cnt = 0;
            __threadfence();
            atomicExch(&g_bar_gen, my + 1);
        } else {
            while (*((volatile int*)&g_bar_gen) == my) {}
        }
        __threadfence();
    }
    __syncthreads();
}

// -------- tile prefetch: idx + F rows via cp.async --------
__device__ __forceinline__ void prefetch_tile(uint32_t A0, char* smb, int e, int base,
                                              int cnt, int ibuf, int t) {
    if (t < TILE_P) {
        int gi = base + t;
        int idxv = (gi < cnt) ? g_idx[e * NPTS + gi] : -1;
        ((int*)(smb + SH_IDX))[ibuf * TILE_P + t] = idxv;
        int real = idxv < 0 ? 0 : idxv;
        const char* src = (const char*)(g_xh + (size_t)real * KPAD);
        uint32_t dst = A0 + SH_F + t * 208;
#pragma unroll
        for (int j = 0; j < 12; j++) cpa16(dst + j * 16, src + j * 16);
    }
}

// -------- expert weight load --------
__device__ __forceinline__ void load_expert(uint32_t A0, char* smb, int e, int t,
                                            const float* b1, const float* b2,
                                            const float* W3, const float* b3) {
    {
        const char* src = (const char*)(g_w1t + ((size_t)e * NH + t) * KPAD);
        uint32_t dst = A0 + SH_W1 + t * 208;
#pragma unroll
        for (int j = 0; j < 12; j++) cpa16(dst + j * 16, src + j * 16);
    }
    {
        const char* src = (const char*)(g_w2t + ((size_t)e * NH + t) * NH);
        uint32_t dst = A0 + SH_W2 + t * 528;
#pragma unroll
        for (int j = 0; j < 32; j++) cpa16(dst + j * 16, src + j * 16);
    }
    if (t < 64) cpa16(A0 + SH_B1 + t * 16, (const char*)(b1 + e * NH) + t * 16);
    else if (t < 128) cpa16(A0 + SH_B2 + (t - 64) * 16, (const char*)(b2 + e * NH) + (t - 64) * 16);
    {
        __half* w3t = (__half*)(smb + SH_W3T);
        for (int i = t; i < 4 * 256; i += THREADS) {       // zero rows 4..7
            int r = i >> 8, k = i & 255;
            w3t[(4 + r) * 264 + k] = __half(0.f);
        }
        for (int i = t; i < 4 * 256; i += THREADS) {       // rows 0..3 = W3^T
            int o = i >> 8, k = i & 255;
            w3t[o * 264 + k] = __float2half_rn(W3[e * NH * DOUT + k * DOUT + o]);
        }
    }
    if (t < 4) ((float*)(smb + SH_B3))[t] = b3[e * DOUT + t];
}

// -------- fused persistent kernel: prep + routing + MLP --------
__global__ __launch_bounds__(THREADS, 1)
void fused_kernel(const float* __restrict__ x, const float* __restrict__ cent,
                  const float* __restrict__ W1, const float* __restrict__ b1,
                  const float* __restrict__ W2, const float* __restrict__ b2,
                  const float* __restrict__ W3, const float* __restrict__ b3,
                  float* __restrict__ out) {
    extern __shared__ char smb[];
    const uint32_t A0 = smem_u32(smb);
    const int t = threadIdx.x;
    const int bid = blockIdx.x;

    // ---- phase A0: zero counters (all CTAs write 0: benign race) ----
    if (t < NE) g_cnt[t] = 0;
    grid_barrier(t);

    // ---- phase A1: weight fp16 convert (strided slice) ----
    for (int i = bid * THREADS + t; i < WCONV_TOTAL; i += GRID_P * THREADS) {
        if (i < NE * NH * KPAD) {
            int e = i / (NH * KPAD);
            int rr = i - e * NH * KPAD;
            int n = rr / KPAD, k = rr - n * KPAD;
            g_w1t[i] = (k < DIN) ? __float2half_rn(W1[(e * DIN + k) * NH + n]) : __half(0.f);
        } else {
            int r = i - NE * NH * KPAD;
            int e = r >> 16;
            int rr = r & 65535;
            int n = rr >> 8, k = rr & 255;
            g_w2t[r] = __float2half_rn(W2[(e << 16) + (k << 8) + n]);
        }
    }

    // ---- phase A2: routing slabs (smem-staged, coalesced) ----
    {
        float* sx = (float*)smb;    // 128*93*4 = 47,616B
        for (int b = bid; b < ROUTE_SLABS; b += GRID_P) {
            const int base = b * 128;
            __syncthreads();       // prev slab reads done
            for (int i = t; i < 128 * XROW; i += THREADS) sx[i] = x[(size_t)base * XROW + i];
            __syncthreads();

            if (t < 128) {
                const int p = t;
                const float px = sx[p * XROW + 0];
                const float py = sx[p * XROW + 1];
                const float pz = sx[p * XROW + 2];
                float d[NE];
                float dmin = 3.4e38f;
#pragma unroll
                for (int e = 0; e < NE; e++) {
                    float dx = px - __ldg(cent + e * 3 + 0);
                    float dy = py - __ldg(cent + e * 3 + 1);
                    float dz = pz - __ldg(cent + e * 3 + 2);
                    d[e] = sqrtf(dx * dx + dy * dy + dz * dz);
                    dmin = fminf(dmin, d[e]);
                }
                float inv[NE];
                float s = 0.f;
#pragma unroll
                for (int e = 0; e < NE; e++) {
                    float v = 1.0f / (d[e] + 1e-8f);
                    if (d[e] > 2.0f * dmin) v = 0.f;
                    inv[e] = v;
                    s += v;
                }
                float rs = 1.0f / s;
                const int n = base + p;
#pragma unroll
                for (int e = 0; e < NE; e++) {
                    float w = inv[e] * rs;
                    g_w[n * NE + e] = w;
                    if (w > 0.f) {
                        int pos = atomicAdd(&g_cnt[e], 1);
                        g_idx[e * NPTS + pos] = n;
                    }
                }
                *reinterpret_cast<float4*>(out + (size_t)n * 4) =
                    make_float4(0.f, 0.f, 0.f, 0.f);
            }

            for (int i = t; i < 128 * 48; i += THREADS) {
                int p = i / 48, kp = i - p * 48;
                int k = 2 * kp;
                float a = (k < DIN) ? sx[p * XROW + 3 + k] : 0.f;
                float bq = (k + 1 < DIN) ? sx[p * XROW + 4 + k] : 0.f;
                ((__half2*)g_xh)[(size_t)(base + p) * 48 + kp] = __floats2half2_rn(a, bq);
            }
        }
    }
    grid_barrier(t);               // routing + weights globally visible

    // ---- phase B: persistent MLP ----
    int tp[NE + 1];
    {
        int run = 0;
#pragma unroll
        for (int e = 0; e < NE; e++) {
            tp[e] = run;
            run += (g_cnt[e] + TILE_P - 1) / TILE_P;
        }
        tp[NE] = run;
    }
    const int total = tp[NE];
    const int lo = (int)(((long long)bid * total) / GRID_P);
    const int hi = (int)(((long long)(bid + 1) * total) / GRID_P);
    if (lo >= hi) return;

    const int wid = t >> 5, lane = t & 31;
    const int g = lane >> 2, tg = lane & 3;
    const int m0 = wid * 16;

    const uint32_t aBase = A0 + SH_F + (m0 + (lane & 15)) * 208 + (lane >> 4) * 16;
    const uint32_t rowpat = (uint32_t)((lane & 7) + ((lane >> 4) << 3));
    const uint32_t colpat = (uint32_t)(((lane >> 3) & 1) * 16);
    const uint32_t bRow1 = A0 + SH_W1 + rowpat * 208 + colpat;
    const uint32_t bRow2 = A0 + SH_W2 + rowpat * 528 + colpat;
    const uint32_t wRow3 = A0 + SH_W3T + (uint32_t)(lane & 7) * 528 + colpat;

    int cur_e = -1;
    int cbuf = 0;
    {
        int e0 = 0;
#pragma unroll
        for (int k = 1; k < NE; k++) if (lo >= tp[k]) e0 = k;
        prefetch_tile(A0, smb, e0, (lo - tp[e0]) * TILE_P, g_cnt[e0], 0, t);
        cpa_commit();
    }

    for (int tt = lo; tt < hi; tt++) {
        int e = 0;
#pragma unroll
        for (int k = 1; k < NE; k++) if (tt >= tp[k]) e = k;

        cpa_wait0();
        __syncthreads();                       // F(tt)+idx ready; prev tile done
        if (e != cur_e) {
            load_expert(A0, smb, e, t, b1, b2, W3, b3);
            cpa_commit();
            cpa_wait0();
            __syncthreads();
            cur_e = e;
        }

        // ---- A1 fragment preload (then F is free) ----
        uint32_t A1[6][4];
#pragma unroll
        for (int s = 0; s < 6; s++)
            ldsm4(A1[s][0], A1[s][1], A1[s][2], A1[s][3], aBase + s * 32);
        __syncthreads();                       // F buffer free

        if (tt + 1 < hi) {
            int e2 = 0;
#pragma unroll
            for (int k = 1; k < NE; k++) if (tt + 1 >= tp[k]) e2 = k;
            prefetch_tile(A0, smb, e2, (tt + 1 - tp[e2]) * TILE_P, g_cnt[e2], cbuf ^ 1, t);
            cpa_commit();
        }

        // ---- layer 1: hA = fp16 A-fragments of relu(F@W1^T + b1) ----
        uint32_t hA[64];
#pragma unroll
        for (int qpp = 0; qpp < 8; qpp++) {
            float C[16];
#pragma unroll
            for (int i = 0; i < 16; i++) C[i] = 0.f;
            uint32_t bbA = bRow1 + (qpp * 32) * 208;
            uint32_t bbB = bbA + 16 * 208;
            uint32_t bf[2][8];
            ldsm4(bf[0][0], bf[0][1], bf[0][2], bf[0][3], bbA);
            ldsm4(bf[0][4], bf[0][5], bf[0][6], bf[0][7], bbB);
#pragma unroll
            for (int s = 0; s < 6; s++) {
                int cu = s & 1;
                if (s < 5) {
                    ldsm4(bf[cu ^ 1][0], bf[cu ^ 1][1], bf[cu ^ 1][2], bf[cu ^ 1][3],
                          bbA + (s + 1) * 32);
                    ldsm4(bf[cu ^ 1][4], bf[cu ^ 1][5], bf[cu ^ 1][6], bf[cu ^ 1][7],
                          bbB + (s + 1) * 32);
                }
                mma16816(C + 0,  A1[s], bf[cu][0], bf[cu][1]);
                mma16816(C + 4,  A1[s], bf[cu][2], bf[cu][3]);
                mma16816(C + 8,  A1[s], bf[cu][4], bf[cu][5]);
                mma16816(C + 12, A1[s], bf[cu][6], bf[cu][7]);
            }
#pragma unroll
            for (int h = 0; h < 2; h++) {
                int colb = 32 * qpp + 16 * h;
                float2 ba = *(float2*)(smb + SH_B1 + (colb + 2 * tg) * 4);
                float2 bb = *(float2*)(smb + SH_B1 + (colb + 8 + 2 * tg) * 4);
                const float* Cc = C + 8 * h;
                hA[8 * qpp + 4 * h + 0] = pack2(fmaxf(Cc[0] + ba.x, 0.f), fmaxf(Cc[1] + ba.y, 0.f));
                hA[8 * qpp + 4 * h + 1] = pack2(fmaxf(Cc[2] + ba.x, 0.f), fmaxf(Cc[3] + ba.y, 0.f));
                hA[8 * qpp + 4 * h + 2] = pack2(fmaxf(Cc[4] + bb.x, 0.f), fmaxf(Cc[5] + bb.y, 0.f));
                hA[8 * qpp + 4 * h + 3] = pack2(fmaxf(Cc[6] + bb.x, 0.f), fmaxf(Cc[7] + bb.y, 0.f));
            }
        }

        // ---- layer 2 + fused layer-3 mma ----
        float C3[4] = {0.f, 0.f, 0.f, 0.f};
#pragma unroll
        for (int qpp = 0; qpp < 8; qpp++) {
            float C[16];
#pragma unroll
            for (int i = 0; i < 16; i++) C[i] = 0.f;
            uint32_t bbA = bRow2 + (qpp * 32) * 528;
            uint32_t bbB = bbA + 16 * 528;
            uint32_t bf[2][8];
            ldsm4(bf[0][0], bf[0][1], bf[0][2], bf[0][3], bbA);
            ldsm4(bf[0][4], bf[0][5], bf[0][6], bf[0][7], bbB);
#pragma unroll
            for (int s = 0; s < 16; s++) {
                int cu = s & 1;
                if (s < 15) {
                    ldsm4(bf[cu ^ 1][0], bf[cu ^ 1][1], bf[cu ^ 1][2], bf[cu ^ 1][3],
                          bbA + (s + 1) * 32);
                    ldsm4(bf[cu ^ 1][4], bf[cu ^ 1][5], bf[cu ^ 1][6], bf[cu ^ 1][7],
                          bbB + (s + 1) * 32);
                }
                mma16816(C + 0,  &hA[4 * s], bf[cu][0], bf[cu][1]);
                mma16816(C + 4,  &hA[4 * s], bf[cu][2], bf[cu][3]);
                mma16816(C + 8,  &hA[4 * s], bf[cu][4], bf[cu][5]);
                mma16816(C + 12, &hA[4 * s], bf[cu][6], bf[cu][7]);
            }
#pragma unroll
            for (int h = 0; h < 2; h++) {
                int colb = 32 * qpp + 16 * h;
                float2 ba = *(float2*)(smb + SH_B2 + (colb + 2 * tg) * 4);
                float2 bb = *(float2*)(smb + SH_B2 + (colb + 8 + 2 * tg) * 4);
                const float* Cc = C + 8 * h;
                uint32_t a2[4];
                a2[0] = pack2(fmaxf(Cc[0] + ba.x, 0.f), fmaxf(Cc[1] + ba.y, 0.f));
                a2[1] = pack2(fmaxf(Cc[2] + ba.x, 0.f), fmaxf(Cc[3] + ba.y, 0.f));
                a2[2] = pack2(fmaxf(Cc[4] + bb.x, 0.f), fmaxf(Cc[5] + bb.y, 0.f));
                a2[3] = pack2(fmaxf(Cc[6] + bb.x, 0.f), fmaxf(Cc[7] + bb.y, 0.f));
                uint32_t w0, w1r;
                ldsm2(w0, w1r, wRow3 + (2 * qpp + h) * 32);
                mma16816(C3, a2, w0, w1r);
            }
        }

        // ---- weighted scatter (C3 cols 0-3 valid; rows m0+g, m0+8+g) ----
        if (tg < 2) {
            const int* sIdxCur = (const int*)(smb + SH_IDX) + cbuf * TILE_P;
            const float* sb3 = (const float*)(smb + SH_B3);
            int col = 2 * tg;
            float b3a = sb3[col], b3b = sb3[col + 1];
            int n0i = sIdxCur[m0 + g];
            int n1i = sIdxCur[m0 + g + 8];
            if (n0i >= 0) {
                float w = g_w[n0i * NE + e];
                atomicAdd(&out[n0i * 4 + col],     w * (C3[0] + b3a));
                atomicAdd(&out[n0i * 4 + col + 1], w * (C3[1] + b3b));
            }
            if (n1i >= 0) {
                float w = g_w[n1i * NE + e];
                atomicAdd(&out[n1i * 4 + col],     w * (C3[2] + b3a));
                atomicAdd(&out[n1i * 4 + col + 1], w * (C3[3] + b3b));
            }
        }
        cbuf ^= 1;
    }
}

// -------- launch --------
extern "C" void kernel_launch(void* const* d_in, const int* in_sizes, int n_in,
                              void* d_out, int out_size) {
    const float* x    = (const float*)d_in[0];
    const float* cent = (const float*)d_in[1];
    const float* W1   = (const float*)d_in[2];
    const float* b1   = (const float*)d_in[3];
    const float* W2   = (const float*)d_in[4];
    const float* b2   = (const float*)d_in[5];
    const float* W3   = (const float*)d_in[6];
    const float* b3   = (const float*)d_in[7];
    float* out = (float*)d_out;

    cudaFuncSetAttribute(fused_kernel, cudaFuncAttributeMaxDynamicSharedMemorySize,
                         SMEM_BYTES);

    fused_kernel<<<GRID_P, THREADS, SMEM_BYTES>>>(x, cent, W1, b1, W2, b2, W3, b3, out);
}

// round 17
// speedup vs baseline: 1.1429x; 1.1429x over previous
#include <cuda_runtime.h>
#include <cuda_fp16.h>
#include <cstdint>

#define NPTS 65536
#define NE 8
#define DIN 90
#define NH 256
#define DOUT 4
#define XROW 93
#define TILE_P 128
#define KPAD 96
#define THREADS 256
#define GRID_P 148

// smem byte offsets (strides 208B=13*16, 528B=33*16 -> ldmatrix conflict-free)
#define SH_W1   0           // W1T [256][104h]    53,248B (expert-resident)
#define SH_W2   53248       // W2T [256][264h]   135,168B (expert-resident)
#define SH_W3T  188416      // W3T [8][264h]       4,224B (rows 0-3 data, 4-7 zero), ldsm.x2
#define SH_F    196864      // F   [128][104h]    26,624B (per tile)
#define SH_B1   223488      // b1 f32 [256]
#define SH_B2   224512      // b2 f32 [256]
#define SH_B3   225536      // b3 f32 [4]
#define SH_IDX  225552      // idx [2][128] int
#define SMEM_BYTES 226576

// -------- device scratch --------
__device__ float  g_w[NPTS * NE];
__device__ int    g_idx[NE * NPTS];
__device__ int    g_cnt[NE];
__device__ __half g_xh[NPTS * KPAD];
__device__ __half g_w1t[NE * NH * KPAD];
__device__ __half g_w2t[NE * NH * NH];

#define WCONV_TOTAL (NE * NH * KPAD + NE * NH * NH)
#define ROUTE_BLOCKS (NPTS / 128)                         // 512
#define CONV_BLOCKS ((WCONV_TOTAL + 511) / 512)           // 1408
#define PREP_BLOCKS (ROUTE_BLOCKS + CONV_BLOCKS)

// -------- PTX helpers --------
__device__ __forceinline__ uint32_t smem_u32(const void* p) {
    uint32_t a;
    asm("{ .reg .u64 t; cvta.to.shared.u64 t, %1; cvt.u32.u64 %0, t; }" : "=r"(a) : "l"(p));
    return a;
}
__device__ __forceinline__ void ldsm4(uint32_t& r0, uint32_t& r1, uint32_t& r2, uint32_t& r3,
                                      uint32_t addr) {
    asm volatile("ldmatrix.sync.aligned.m8n8.x4.shared.b16 {%0,%1,%2,%3}, [%4];"
                 : "=r"(r0), "=r"(r1), "=r"(r2), "=r"(r3) : "r"(addr));
}
__device__ __forceinline__ void ldsm2(uint32_t& r0, uint32_t& r1, uint32_t addr) {
    asm volatile("ldmatrix.sync.aligned.m8n8.x2.shared.b16 {%0,%1}, [%2];"
                 : "=r"(r0), "=r"(r1) : "r"(addr));
}
__device__ __forceinline__ void mma16816(float* c, const uint32_t* a, uint32_t b0, uint32_t b1) {
    asm volatile(
        "mma.sync.aligned.m16n8k16.row.col.f32.f16.f16.f32 "
        "{%0,%1,%2,%3}, {%4,%5,%6,%7}, {%8,%9}, {%0,%1,%2,%3};"
        : "+f"(c[0]), "+f"(c[1]), "+f"(c[2]), "+f"(c[3])
        : "r"(a[0]), "r"(a[1]), "r"(a[2]), "r"(a[3]), "r"(b0), "r"(b1));
}
__device__ __forceinline__ void cpa16(uint32_t dst, const void* src) {
    asm volatile("cp.async.cg.shared.global [%0], [%1], 16;" :: "r"(dst), "l"(src));
}
__device__ __forceinline__ void cpa_commit() { asm volatile("cp.async.commit_group;"); }
__device__ __forceinline__ void cpa_wait0() { asm volatile("cp.async.wait_group 0;" ::: "memory"); }
__device__ __forceinline__ uint32_t pack2(float a, float b) {
    __half2 h = __floats2half2_rn(a, b);
    return *(uint32_t*)&h;
}

// -------- kernel 1: fused prep (routing blocks ∥ weight-convert blocks) --------
// g_cnt is zeroed by a cudaMemsetAsync node BEFORE this kernel.
__global__ void prep_kernel(const float* __restrict__ x,
                            const float* __restrict__ cent,
                            const float* __restrict__ W1,
                            const float* __restrict__ W2,
                            float* __restrict__ out) {
    const int t = threadIdx.x;

    if (blockIdx.x < ROUTE_BLOCKS) {
        __shared__ float sx[128 * XROW];   // 47,616B
        const int base = blockIdx.x * 128;

        for (int i = t; i < 128 * XROW; i += 256) sx[i] = x[(size_t)base * XROW + i];
        __syncthreads();

        if (t < 128) {   // routing math: one point per thread (block row-slab is 128)
            const int p = t;
            const float px = sx[p * XROW + 0];
            const float py = sx[p * XROW + 1];
            const float pz = sx[p * XROW + 2];
            float d[NE];
            float dmin = 3.4e38f;
#pragma unroll
            for (int e = 0; e < NE; e++) {
                float dx = px - __ldg(cent + e * 3 + 0);
                float dy = py - __ldg(cent + e * 3 + 1);
                float dz = pz - __ldg(cent + e * 3 + 2);
                d[e] = sqrtf(dx * dx + dy * dy + dz * dz);
                dmin = fminf(dmin, d[e]);
            }
            float inv[NE];
            float s = 0.f;
#pragma unroll
            for (int e = 0; e < NE; e++) {
                float v = 1.0f / (d[e] + 1e-8f);
                if (d[e] > 2.0f * dmin) v = 0.f;
                inv[e] = v;
                s += v;
            }
            float rs = 1.0f / s;
            const int n = base + p;
#pragma unroll
            for (int e = 0; e < NE; e++) {
                float w = inv[e] * rs;
                g_w[n * NE + e] = w;
                if (w > 0.f) {
                    int pos = atomicAdd(&g_cnt[e], 1);
                    g_idx[e * NPTS + pos] = n;
                }
            }
            *reinterpret_cast<float4*>(out + (size_t)n * 4) = make_float4(0.f, 0.f, 0.f, 0.f);
        }

        // fp16 feature emit: i-indexed, coalesced across the block
        for (int i = t; i < 128 * 48; i += 256) {
            int p = i / 48, kp = i - p * 48;
            int k = 2 * kp;
            float a = (k < DIN) ? sx[p * XROW + 3 + k] : 0.f;
            float b = (k + 1 < DIN) ? sx[p * XROW + 4 + k] : 0.f;
            ((__half2*)g_xh)[(size_t)(base + p) * 48 + kp] = __floats2half2_rn(a, b);
        }
    } else {
        // weight conversion: two items per thread
        int i0 = (blockIdx.x - ROUTE_BLOCKS) * 512 + t * 2;
#pragma unroll
        for (int u = 0; u < 2; u++) {
            int i = i0 + u;
            if (i < NE * NH * KPAD) {
                int e = i / (NH * KPAD);
                int rr = i - e * NH * KPAD;
                int n = rr / KPAD, k = rr - n * KPAD;
                g_w1t[i] = (k < DIN) ? __float2half_rn(W1[(e * DIN + k) * NH + n]) : __half(0.f);
            } else if (i < WCONV_TOTAL) {
                int r = i - NE * NH * KPAD;
                int e = r >> 16;
                int rr = r & 65535;
                int n = rr >> 8, k = rr & 255;
                g_w2t[r] = __float2half_rn(W2[(e << 16) + (k << 8) + n]);
            }
        }
    }
}

// -------- tile prefetch: idx + F rows via cp.async --------
__device__ __forceinline__ void prefetch_tile(uint32_t A0, char* smb, int e, int base,
                                              int cnt, int ibuf, int t) {
    if (t < TILE_P) {
        int gi = base + t;
        int idxv = (gi < cnt) ? g_idx[e * NPTS + gi] : -1;
        ((int*)(smb + SH_IDX))[ibuf * TILE_P + t] = idxv;
        int real = idxv < 0 ? 0 : idxv;
        const char* src = (const char*)(g_xh + (size_t)real * KPAD);
        uint32_t dst = A0 + SH_F + t * 208;
#pragma unroll
        for (int j = 0; j < 12; j++) cpa16(dst + j * 16, src + j * 16);
    }
}

// -------- expert weight load --------
__device__ __forceinline__ void load_expert(uint32_t A0, char* smb, int e, int t,
                                            const float* b1, const float* b2,
                                            const float* W3, const float* b3) {
    {
        const char* src = (const char*)(g_w1t + ((size_t)e * NH + t) * KPAD);
        uint32_t dst = A0 + SH_W1 + t * 208;
#pragma unroll
        for (int j = 0; j < 12; j++) cpa16(dst + j * 16, src + j * 16);
    }
    {
        const char* src = (const char*)(g_w2t + ((size_t)e * NH + t) * NH);
        uint32_t dst = A0 + SH_W2 + t * 528;
#pragma unroll
        for (int j = 0; j < 32; j++) cpa16(dst + j * 16, src + j * 16);
    }
    if (t < 64) cpa16(A0 + SH_B1 + t * 16, (const char*)(b1 + e * NH) + t * 16);
    else if (t < 128) cpa16(A0 + SH_B2 + (t - 64) * 16, (const char*)(b2 + e * NH) + (t - 64) * 16);
    {
        __half* w3t = (__half*)(smb + SH_W3T);
        for (int i = t; i < 4 * 256; i += THREADS) {       // zero rows 4..7
            int r = i >> 8, k = i & 255;
            w3t[(4 + r) * 264 + k] = __half(0.f);
        }
        for (int i = t; i < 4 * 256; i += THREADS) {       // rows 0..3 = W3^T
            int o = i >> 8, k = i & 255;
            w3t[o * 264 + k] = __float2half_rn(W3[e * NH * DOUT + k * DOUT + o]);
        }
    }
    if (t < 4) ((float*)(smb + SH_B3))[t] = b3[e * DOUT + t];
}

// -------- kernel 2: persistent fused MLP (8 warps, m16/warp, reg-resident hA) --------
__global__ __launch_bounds__(THREADS, 1)
void mlp_persist_kernel(const float* __restrict__ b1, const float* __restrict__ b2,
                        const float* __restrict__ W3, const float* __restrict__ b3,
                        float* __restrict__ out) {
    int tp[NE + 1];
    {
        int run = 0;
#pragma unroll
        for (int e = 0; e < NE; e++) {
            tp[e] = run;
            run += (g_cnt[e] + TILE_P - 1) / TILE_P;
        }
        tp[NE] = run;
    }
    const int total = tp[NE];
    const int G = gridDim.x;
    const int lo = (int)(((long long)blockIdx.x * total) / G);
    const int hi = (int)(((long long)(blockIdx.x + 1) * total) / G);
    if (lo >= hi) return;

    extern __shared__ char smb[];
    const uint32_t A0 = smem_u32(smb);
    const int t = threadIdx.x;
    const int wid = t >> 5, lane = t & 31;
    const int g = lane >> 2, tg = lane & 3;
    const int m0 = wid * 16;

    const uint32_t aBase = A0 + SH_F + (m0 + (lane & 15)) * 208 + (lane >> 4) * 16;
    const uint32_t rowpat = (uint32_t)((lane & 7) + ((lane >> 4) << 3));
    const uint32_t colpat = (uint32_t)(((lane >> 3) & 1) * 16);
    const uint32_t bRow1 = A0 + SH_W1 + rowpat * 208 + colpat;
    const uint32_t bRow2 = A0 + SH_W2 + rowpat * 528 + colpat;
    const uint32_t wRow3 = A0 + SH_W3T + (uint32_t)(lane & 7) * 528 + colpat;

    int cur_e = -1;
    int cbuf = 0;
    {
        int e0 = 0;
#pragma unroll
        for (int k = 1; k < NE; k++) if (lo >= tp[k]) e0 = k;
        prefetch_tile(A0, smb, e0, (lo - tp[e0]) * TILE_P, g_cnt[e0], 0, t);
        cpa_commit();
    }

    for (int tt = lo; tt < hi; tt++) {
        int e = 0;
#pragma unroll
        for (int k = 1; k < NE; k++) if (tt >= tp[k]) e = k;

        cpa_wait0();
        __syncthreads();                       // F(tt)+idx ready; prev tile done
        if (e != cur_e) {
            load_expert(A0, smb, e, t, b1, b2, W3, b3);
            cpa_commit();
            cpa_wait0();
            __syncthreads();
            cur_e = e;
        }

        // ---- A1 fragment preload (then F is free) ----
        uint32_t A1[6][4];
#pragma unroll
        for (int s = 0; s < 6; s++)
            ldsm4(A1[s][0], A1[s][1], A1[s][2], A1[s][3], aBase + s * 32);
        __syncthreads();                       // F buffer free

        if (tt + 1 < hi) {
            int e2 = 0;
#pragma unroll
            for (int k = 1; k < NE; k++) if (tt + 1 >= tp[k]) e2 = k;
            prefetch_tile(A0, smb, e2, (tt + 1 - tp[e2]) * TILE_P, g_cnt[e2], cbuf ^ 1, t);
            cpa_commit();
        }

        // ---- layer 1: hA = fp16 A-fragments of relu(F@W1^T + b1) ----
        uint32_t hA[64];
#pragma unroll
        for (int qpp = 0; qpp < 8; qpp++) {
            float C[16];
#pragma unroll
            for (int i = 0; i < 16; i++) C[i] = 0.f;
            uint32_t bbA = bRow1 + (qpp * 32) * 208;
            uint32_t bbB = bbA + 16 * 208;
            uint32_t bf[2][8];
            ldsm4(bf[0][0], bf[0][1], bf[0][2], bf[0][3], bbA);
            ldsm4(bf[0][4], bf[0][5], bf[0][6], bf[0][7], bbB);
#pragma unroll
            for (int s = 0; s < 6; s++) {
                int cu = s & 1;
                if (s < 5) {
                    ldsm4(bf[cu ^ 1][0], bf[cu ^ 1][1], bf[cu ^ 1][2], bf[cu ^ 1][3],
                          bbA + (s + 1) * 32);
                    ldsm4(bf[cu ^ 1][4], bf[cu ^ 1][5], bf[cu ^ 1][6], bf[cu ^ 1][7],
                          bbB + (s + 1) * 32);
                }
                mma16816(C + 0,  A1[s], bf[cu][0], bf[cu][1]);
                mma16816(C + 4,  A1[s], bf[cu][2], bf[cu][3]);
                mma16816(C + 8,  A1[s], bf[cu][4], bf[cu][5]);
                mma16816(C + 12, A1[s], bf[cu][6], bf[cu][7]);
            }
#pragma unroll
            for (int h = 0; h < 2; h++) {
                int colb = 32 * qpp + 16 * h;
                float2 ba = *(float2*)(smb + SH_B1 + (colb + 2 * tg) * 4);
                float2 bb = *(float2*)(smb + SH_B1 + (colb + 8 + 2 * tg) * 4);
                const float* Cc = C + 8 * h;
                hA[8 * qpp + 4 * h + 0] = pack2(fmaxf(Cc[0] + ba.x, 0.f), fmaxf(Cc[1] + ba.y, 0.f));
                hA[8 * qpp + 4 * h + 1] = pack2(fmaxf(Cc[2] + ba.x, 0.f), fmaxf(Cc[3] + ba.y, 0.f));
                hA[8 * qpp + 4 * h + 2] = pack2(fmaxf(Cc[4] + bb.x, 0.f), fmaxf(Cc[5] + bb.y, 0.f));
                hA[8 * qpp + 4 * h + 3] = pack2(fmaxf(Cc[6] + bb.x, 0.f), fmaxf(Cc[7] + bb.y, 0.f));
            }
        }

        // ---- layer 2 + fused layer-3 mma ----
        float C3[4] = {0.f, 0.f, 0.f, 0.f};
#pragma unroll
        for (int qpp = 0; qpp < 8; qpp++) {
            float C[16];
#pragma unroll
            for (int i = 0; i < 16; i++) C[i] = 0.f;
            uint32_t bbA = bRow2 + (qpp * 32) * 528;
            uint32_t bbB = bbA + 16 * 528;
            uint32_t bf[2][8];
            ldsm4(bf[0][0], bf[0][1], bf[0][2], bf[0][3], bbA);
            ldsm4(bf[0][4], bf[0][5], bf[0][6], bf[0][7], bbB);
#pragma unroll
            for (int s = 0; s < 16; s++) {
                int cu = s & 1;
                if (s < 15) {
                    ldsm4(bf[cu ^ 1][0], bf[cu ^ 1][1], bf[cu ^ 1][2], bf[cu ^ 1][3],
                          bbA + (s + 1) * 32);
                    ldsm4(bf[cu ^ 1][4], bf[cu ^ 1][5], bf[cu ^ 1][6], bf[cu ^ 1][7],
                          bbB + (s + 1) * 32);
                }
                mma16816(C + 0,  &hA[4 * s], bf[cu][0], bf[cu][1]);
                mma16816(C + 4,  &hA[4 * s], bf[cu][2], bf[cu][3]);
                mma16816(C + 8,  &hA[4 * s], bf[cu][4], bf[cu][5]);
                mma16816(C + 12, &hA[4 * s], bf[cu][6], bf[cu][7]);
            }
#pragma unroll
            for (int h = 0; h < 2; h++) {
                int colb = 32 * qpp + 16 * h;
                float2 ba = *(float2*)(smb + SH_B2 + (colb + 2 * tg) * 4);
                float2 bb = *(float2*)(smb + SH_B2 + (colb + 8 + 2 * tg) * 4);
                const float* Cc = C + 8 * h;
                uint32_t a2[4];
                a2[0] = pack2(fmaxf(Cc[0] + ba.x, 0.f), fmaxf(Cc[1] + ba.y, 0.f));
                a2[1] = pack2(fmaxf(Cc[2] + ba.x, 0.f), fmaxf(Cc[3] + ba.y, 0.f));
                a2[2] = pack2(fmaxf(Cc[4] + bb.x, 0.f), fmaxf(Cc[5] + bb.y, 0.f));
                a2[3] = pack2(fmaxf(Cc[6] + bb.x, 0.f), fmaxf(Cc[7] + bb.y, 0.f));
                uint32_t w0, w1r;
                ldsm2(w0, w1r, wRow3 + (2 * qpp + h) * 32);
                mma16816(C3, a2, w0, w1r);
            }
        }

        // ---- weighted scatter (C3 cols 0-3 valid; rows m0+g, m0+8+g) ----
        if (tg < 2) {
            const int* sIdxCur = (const int*)(smb + SH_IDX) + cbuf * TILE_P;
            const float* sb3 = (const float*)(smb + SH_B3);
            int col = 2 * tg;
            float b3a = sb3[col], b3b = sb3[col + 1];
            int n0i = sIdxCur[m0 + g];
            int n1i = sIdxCur[m0 + g + 8];
            if (n0i >= 0) {
                float w = g_w[n0i * NE + e];
                atomicAdd(&out[n0i * 4 + col],     w * (C3[0] + b3a));
                atomicAdd(&out[n0i * 4 + col + 1], w * (C3[1] + b3b));
            }
            if (n1i >= 0) {
                float w = g_w[n1i * NE + e];
                atomicAdd(&out[n1i * 4 + col],     w * (C3[2] + b3a));
                atomicAdd(&out[n1i * 4 + col + 1], w * (C3[3] + b3b));
            }
        }
        cbuf ^= 1;
    }
}

// -------- launch --------
extern "C" void kernel_launch(void* const* d_in, const int* in_sizes, int n_in,
                              void* d_out, int out_size) {
    const float* x    = (const float*)d_in[0];
    const float* cent = (const float*)d_in[1];
    const float* W1   = (const float*)d_in[2];
    const float* b1   = (const float*)d_in[3];
    const float* W2   = (const float*)d_in[4];
    const float* b2   = (const float*)d_in[5];
    const float* W3   = (const float*)d_in[6];
    const float* b3   = (const float*)d_in[7];
    float* out = (float*)d_out;

    cudaFuncSetAttribute(mlp_persist_kernel, cudaFuncAttributeMaxDynamicSharedMemorySize,
                         SMEM_BYTES);

    // zero g_cnt via memset node (graph-legal; orders before prep on the stream)
    void* cnt_addr = nullptr;
    cudaGetSymbolAddress(&cnt_addr, g_cnt);
    cudaMemsetAsync(cnt_addr, 0, NE * sizeof(int));

    prep_kernel<<<PREP_BLOCKS, 256>>>(x, cent, W1, W2, out);
    mlp_persist_kernel<<<GRID_P, THREADS, SMEM_BYTES>>>(b1, b2, W3, b3, out);
}